// round 1
// baseline (speedup 1.0000x reference)
#include <cuda_runtime.h>
#include <math.h>
#include <stdint.h>

// Problem dims (fixed by the reference)
#define BSZ     4
#define SEQ     2048
#define DMODEL  2048
#define DINNER  4096
#define MTOT    (BSZ * SEQ)        // 8192 rows
#define N1      (2 * DINNER)       // 8192 (x_proj width)
#define K1      DMODEL             // 2048
#define N2      DMODEL             // 2048
#define K2      DINNER             // 4096

// Scratch (device globals — no runtime allocation allowed)
__device__ float g_xproj[(size_t)MTOT * N1];   // [8192, 8192] fp32 = 256 MB
__device__ float g_h[(size_t)MTOT * K2];       // [8192, 4096] fp32 = 128 MB

// ---------------------------------------------------------------------------
// Generic NT GEMM: C[M,N] = A[M,K] * B[N,K]^T, all row-major, K contiguous.
// BM=BN=128, BK=16, 256 threads, 8x8 register tile per thread.
// Requires M%128==0, N%128==0, K%16==0 (true for all our shapes).
// ---------------------------------------------------------------------------
template <int BM, int BN, int BK, int TM, int TN>
__global__ __launch_bounds__(256, 2)
void gemm_nt(const float* __restrict__ A, const float* __restrict__ B,
             float* __restrict__ C, int M, int N, int K) {
    __shared__ float As[BK][BM + 4];
    __shared__ float Bs[BK][BN + 4];

    const int tid = threadIdx.x;             // 0..255
    const int tx  = tid % (BN / TN);          // 0..15 (n direction)
    const int ty  = tid / (BN / TN);          // 0..15 (m direction)
    const int m0  = blockIdx.y * BM;
    const int n0  = blockIdx.x * BN;

    float acc[TM][TN];
#pragma unroll
    for (int i = 0; i < TM; i++)
#pragma unroll
        for (int j = 0; j < TN; j++) acc[i][j] = 0.f;

    for (int k0 = 0; k0 < K; k0 += BK) {
        // Load A tile (BM x BK) transposed into As: 512 float4 loads, 2 per thread
#pragma unroll
        for (int i = 0; i < 2; i++) {
            int lin = tid + i * 256;          // 0..511
            int row = lin >> 2;               // 0..127
            int c4  = lin & 3;                // 0..3
            float4 v = *reinterpret_cast<const float4*>(
                &A[(size_t)(m0 + row) * K + k0 + c4 * 4]);
            As[c4 * 4 + 0][row] = v.x;
            As[c4 * 4 + 1][row] = v.y;
            As[c4 * 4 + 2][row] = v.z;
            As[c4 * 4 + 3][row] = v.w;
        }
        // Load B tile (BN x BK) transposed into Bs
#pragma unroll
        for (int i = 0; i < 2; i++) {
            int lin = tid + i * 256;
            int row = lin >> 2;
            int c4  = lin & 3;
            float4 v = *reinterpret_cast<const float4*>(
                &B[(size_t)(n0 + row) * K + k0 + c4 * 4]);
            Bs[c4 * 4 + 0][row] = v.x;
            Bs[c4 * 4 + 1][row] = v.y;
            Bs[c4 * 4 + 2][row] = v.z;
            Bs[c4 * 4 + 3][row] = v.w;
        }
        __syncthreads();

#pragma unroll
        for (int k = 0; k < BK; k++) {
            float a[TM], b[TN];
#pragma unroll
            for (int i = 0; i < TM; i++) a[i] = As[k][ty * TM + i];
#pragma unroll
            for (int j = 0; j < TN; j++) b[j] = Bs[k][tx * TN + j];
#pragma unroll
            for (int i = 0; i < TM; i++)
#pragma unroll
                for (int j = 0; j < TN; j++)
                    acc[i][j] = fmaf(a[i], b[j], acc[i][j]);
        }
        __syncthreads();
    }

    // Store C tile (vectorized)
#pragma unroll
    for (int i = 0; i < TM; i++) {
        float* crow = &C[(size_t)(m0 + ty * TM + i) * N + n0 + tx * TN];
#pragma unroll
        for (int j = 0; j < TN; j += 4) {
            float4 v = make_float4(acc[i][j], acc[i][j + 1], acc[i][j + 2], acc[i][j + 3]);
            *reinterpret_cast<float4*>(crow + j) = v;
        }
    }
}

// ---------------------------------------------------------------------------
// Depthwise causal conv(D_CONV=4) + bias + SiLU, gated by SiLU(gate), * D.
// x_proj layout: [MTOT, 8192]; xi = cols [0,4096), gate = cols [4096,8192).
// h[m,d] = silu(conv_b[d] + sum_j xi[m - (3-j), d] * conv_w[d,0,j]) * D[d]
//          * silu(xproj[m, 4096+d]),  with taps clipped at t<0 inside batch b.
// ---------------------------------------------------------------------------
__global__ void conv_gate_kernel(const float* __restrict__ xp,
                                 const float* __restrict__ conv_w,
                                 const float* __restrict__ conv_b,
                                 const float* __restrict__ Dvec,
                                 float* __restrict__ h) {
    int idx = blockIdx.x * blockDim.x + threadIdx.x;
    if (idx >= MTOT * DINNER) return;
    int d = idx & (DINNER - 1);
    int m = idx >> 12;            // / DINNER (4096)
    int t = m & (SEQ - 1);        // t within batch (SEQ = 2048)

    const float* base = xp + (size_t)m * N1 + d;
    float xc = conv_b[d];
    // taps: input positions t, t-1, t-2, t-3 multiply conv_w[3],[2],[1],[0]
    xc = fmaf(base[0], conv_w[d * 4 + 3], xc);
    if (t >= 1) xc = fmaf(base[-(ptrdiff_t)N1],     conv_w[d * 4 + 2], xc);
    if (t >= 2) xc = fmaf(base[-2 * (ptrdiff_t)N1], conv_w[d * 4 + 1], xc);
    if (t >= 3) xc = fmaf(base[-3 * (ptrdiff_t)N1], conv_w[d * 4 + 0], xc);

    float gate = xp[(size_t)m * N1 + DINNER + d];
    float s1 = xc   / (1.f + __expf(-xc));
    float s2 = gate / (1.f + __expf(-gate));
    h[idx] = s1 * Dvec[d] * s2;
}

// ---------------------------------------------------------------------------
extern "C" void kernel_launch(void* const* d_in, const int* in_sizes, int n_in,
                              void* d_out, int out_size) {
    const float* x      = (const float*)d_in[0];  // [4,2048,2048]
    const float* w_in   = (const float*)d_in[1];  // [8192,2048]
    const float* w_out  = (const float*)d_in[2];  // [2048,4096]
    const float* conv_w = (const float*)d_in[3];  // [4096,1,4]
    const float* conv_b = (const float*)d_in[4];  // [4096]
    const float* Dvec   = (const float*)d_in[5];  // [4096]
    float*       out    = (float*)d_out;          // [4,2048,2048]

    float* xp = nullptr;
    float* h  = nullptr;
    cudaGetSymbolAddress((void**)&xp, g_xproj);
    cudaGetSymbolAddress((void**)&h,  g_h);

    // GEMM1: x_proj = x @ w_in^T   (M=8192, N=8192, K=2048)
    {
        dim3 grid(N1 / 128, MTOT / 128);
        gemm_nt<128, 128, 16, 8, 8><<<grid, 256>>>(x, w_in, xp, MTOT, N1, K1);
    }

    // conv + gating -> h
    {
        int total = MTOT * DINNER;
        conv_gate_kernel<<<(total + 255) / 256, 256>>>(xp, conv_w, conv_b, Dvec, h);
    }

    // GEMM2: out = h @ w_out^T     (M=8192, N=2048, K=4096)
    {
        dim3 grid(N2 / 128, MTOT / 128);
        gemm_nt<128, 128, 16, 8, 8><<<grid, 256>>>(h, w_out, out, MTOT, N2, K2);
    }
}

// round 3
// speedup vs baseline: 3.7165x; 3.7165x over previous
#include <cuda_runtime.h>
#include <cuda_bf16.h>
#include <stdint.h>

// Problem dims (fixed)
#define MTOT   8192     // B*T
#define SEQ    2048
#define N1     8192     // 2*d_inner
#define K1     2048     // d_model
#define DINNER 4096
#define N2     2048     // d_model
#define K2     4096     // d_inner

// ---------------- scratch (device globals; no runtime alloc) ----------------
__device__ float g_xproj[(size_t)MTOT * N1];                    // 256 MB
__device__ __nv_bfloat16 g_x_hi [(size_t)MTOT * K1];
__device__ __nv_bfloat16 g_x_lo [(size_t)MTOT * K1];
__device__ __nv_bfloat16 g_wi_hi[(size_t)N1 * K1];
__device__ __nv_bfloat16 g_wi_lo[(size_t)N1 * K1];
__device__ __nv_bfloat16 g_h_hi [(size_t)MTOT * K2];
__device__ __nv_bfloat16 g_h_lo [(size_t)MTOT * K2];
__device__ __nv_bfloat16 g_wo_hi[(size_t)N2 * K2];
__device__ __nv_bfloat16 g_wo_lo[(size_t)N2 * K2];

// ---------------- PTX helpers (all legal on plain sm_103) ----------------
__device__ __forceinline__ uint32_t smem_u32(const void* p) {
    uint32_t a;
    asm("{ .reg .u64 t; cvta.to.shared.u64 t, %1; cvt.u32.u64 %0, t; }" : "=r"(a) : "l"(p));
    return a;
}
#define MBAR_INIT(a, c) \
    asm volatile("mbarrier.init.shared.b64 [%0], %1;" :: "r"(a), "r"(c) : "memory")
#define MBAR_EXPECT_TX(a, b) \
    asm volatile("mbarrier.arrive.expect_tx.shared.b64 _, [%0], %1;" :: "r"(a), "r"(b) : "memory")
#define MBAR_ARRIVE(a) \
    asm volatile("mbarrier.arrive.shared.b64 _, [%0];" :: "r"(a) : "memory")
#define MBAR_WAIT(a, ph) do {                                                      \
    uint32_t _m = (a), _p = (ph), _d;                                              \
    asm volatile("{ .reg .pred p; mbarrier.try_wait.parity.acquire.cta.shared::cta.b64 p, [%1], %2;" \
                 " selp.b32 %0, 1, 0, p; }" : "=r"(_d) : "r"(_m), "r"(_p) : "memory"); \
    if (!_d) {                                                                     \
        asm volatile("{ .reg .pred P;\n"                                           \
                     "W%=: mbarrier.try_wait.parity.acquire.cta.shared::cta.b64 P, [%0], %1, 0x989680;\n" \
                     "@P bra.uni D%=;\n bra.uni W%=;\nD%=: }"                      \
                     :: "r"(_m), "r"(_p) : "memory");                              \
    } } while (0)
#define BULK_G2S(sa, gp, bytes, mb) \
    asm volatile("cp.async.bulk.shared::cluster.global.mbarrier::complete_tx::bytes [%0], [%1], %2, [%3];" \
                 :: "r"(sa), "l"(gp), "r"(bytes), "r"(mb) : "memory")

__device__ __forceinline__ void ldsm_x4(uint32_t* r, uint32_t addr) {
    asm volatile("ldmatrix.sync.aligned.m8n8.x4.shared.b16 {%0,%1,%2,%3}, [%4];"
                 : "=r"(r[0]), "=r"(r[1]), "=r"(r[2]), "=r"(r[3]) : "r"(addr));
}
__device__ __forceinline__ void mma_bf16(float* d, const uint32_t* a, const uint32_t* b) {
    asm volatile("mma.sync.aligned.m16n8k16.row.col.f32.bf16.bf16.f32 "
                 "{%0,%1,%2,%3},{%4,%5,%6,%7},{%8,%9},{%0,%1,%2,%3};"
                 : "+f"(d[0]), "+f"(d[1]), "+f"(d[2]), "+f"(d[3])
                 : "r"(a[0]), "r"(a[1]), "r"(a[2]), "r"(a[3]), "r"(b[0]), "r"(b[1]));
}

// Tiled+swizzled bf16 layout: tiles of 128 rows x 64 cols (16 KB), k-tile fastest.
// Within a tile: SW128 swizzle of (row*128 + col*2).
__device__ __forceinline__ size_t tiled_off(int r, int c, int K) {
    size_t tile = ((size_t)(r >> 7) * (size_t)(K >> 6) + (size_t)(c >> 6)) << 14;
    uint32_t off = ((uint32_t)(r & 127) << 7) | ((uint32_t)(c & 63) << 1);
    off ^= (off >> 3) & 0x70;
    return tile + off;
}

// ---------------- split fp32 -> (hi,lo) bf16 in tiled layout ----------------
__global__ void split_tiled(const float* __restrict__ src, __nv_bfloat16* __restrict__ hi,
                            __nv_bfloat16* __restrict__ lo, int total8, int K, int kshift) {
    int idx = blockIdx.x * blockDim.x + threadIdx.x;
    if (idx >= total8) return;
    int e0 = idx << 3;
    int r = e0 >> kshift;
    int c = e0 & (K - 1);
    const float* p = src + (size_t)r * K + c;
    float4 v0 = *reinterpret_cast<const float4*>(p);
    float4 v1 = *reinterpret_cast<const float4*>(p + 4);
    float xs[8] = {v0.x, v0.y, v0.z, v0.w, v1.x, v1.y, v1.z, v1.w};
    __align__(16) __nv_bfloat16 hv[8];
    __align__(16) __nv_bfloat16 lv[8];
#pragma unroll
    for (int j = 0; j < 8; j++) {
        __nv_bfloat16 h = __float2bfloat16(xs[j]);
        hv[j] = h;
        lv[j] = __float2bfloat16(xs[j] - __bfloat162float(h));
    }
    size_t o = tiled_off(r, c, K);
    *reinterpret_cast<uint4*>((char*)hi + o) = *reinterpret_cast<const uint4*>(hv);
    *reinterpret_cast<uint4*>((char*)lo + o) = *reinterpret_cast<const uint4*>(lv);
}

// ------- depthwise causal conv(4) + SiLU gate, output split to bf16 hi/lo -------
__global__ void conv_gate_split(const float* __restrict__ xp, const float* __restrict__ cw,
                                const float* __restrict__ cb, const float* __restrict__ Dv,
                                __nv_bfloat16* __restrict__ hhi, __nv_bfloat16* __restrict__ hlo) {
    int idx = blockIdx.x * blockDim.x + threadIdx.x;
    if (idx >= (MTOT * DINNER) / 8) return;
    int d0 = (idx & 511) << 3;
    int m  = idx >> 9;
    int t  = m & (SEQ - 1);
    const float* row = xp + (size_t)m * N1 + d0;

    float acc[8];
    {
        float4 b0 = *reinterpret_cast<const float4*>(cb + d0);
        float4 b1 = *reinterpret_cast<const float4*>(cb + d0 + 4);
        acc[0]=b0.x; acc[1]=b0.y; acc[2]=b0.z; acc[3]=b0.w;
        acc[4]=b1.x; acc[5]=b1.y; acc[6]=b1.z; acc[7]=b1.w;
    }
    float4 cwv[8];
#pragma unroll
    for (int e = 0; e < 8; e++) cwv[e] = *reinterpret_cast<const float4*>(cw + (size_t)(d0 + e) * 4);

#pragma unroll
    for (int j = 0; j < 4; j++) {
        if (t >= j) {
            const float* rp = row - (size_t)j * N1;
            float4 a = *reinterpret_cast<const float4*>(rp);
            float4 b = *reinterpret_cast<const float4*>(rp + 4);
            float xv[8] = {a.x, a.y, a.z, a.w, b.x, b.y, b.z, b.w};
#pragma unroll
            for (int e = 0; e < 8; e++) {
                float w = (j == 0) ? cwv[e].w : (j == 1) ? cwv[e].z : (j == 2) ? cwv[e].y : cwv[e].x;
                acc[e] = fmaf(xv[e], w, acc[e]);
            }
        }
    }
    float4 g0 = *reinterpret_cast<const float4*>(row + DINNER);
    float4 g1 = *reinterpret_cast<const float4*>(row + DINNER + 4);
    float gv[8] = {g0.x, g0.y, g0.z, g0.w, g1.x, g1.y, g1.z, g1.w};
    float4 dv0 = *reinterpret_cast<const float4*>(Dv + d0);
    float4 dv1 = *reinterpret_cast<const float4*>(Dv + d0 + 4);
    float dv[8] = {dv0.x, dv0.y, dv0.z, dv0.w, dv1.x, dv1.y, dv1.z, dv1.w};

    __align__(16) __nv_bfloat16 hv[8];
    __align__(16) __nv_bfloat16 lv[8];
#pragma unroll
    for (int e = 0; e < 8; e++) {
        float s1 = acc[e] / (1.f + __expf(-acc[e]));
        float s2 = gv[e] / (1.f + __expf(-gv[e]));
        float val = s1 * dv[e] * s2;
        __nv_bfloat16 h = __float2bfloat16(val);
        hv[e] = h;
        lv[e] = __float2bfloat16(val - __bfloat162float(h));
    }
    size_t o = tiled_off(m, d0, K2);
    *reinterpret_cast<uint4*>((char*)hhi + o) = *reinterpret_cast<const uint4*>(hv);
    *reinterpret_cast<uint4*>((char*)hlo + o) = *reinterpret_cast<const uint4*>(lv);
}

// ---------------- bf16x3 HMMA GEMM: C[M,N] = A[M,K] * B[N,K]^T ----------------
// CTA tile 128x128, BK=64, 2-stage async pipeline, 8 compute warps + 1 producer.
// Each compute warp: 64x32 output, m16n8k16 mma.sync, 3 correction terms.
#define TILE_BYTES  16384
#define STAGE_BYTES 65536      // A_hi A_lo B_hi B_lo
#define SMEM_REQ    (2 * STAGE_BYTES + 1024 + 128)

__global__ void __launch_bounds__(288, 1)
gemm_bf16x3(const __nv_bfloat16* __restrict__ Ahi, const __nv_bfloat16* __restrict__ Alo,
            const __nv_bfloat16* __restrict__ Bhi, const __nv_bfloat16* __restrict__ Blo,
            float* __restrict__ C, int M, int N, int K) {
    extern __shared__ char smem_raw[];
    uint32_t sbase = (smem_u32(smem_raw) + 1023) & ~1023u;
    const int tid = threadIdx.x, wid = tid >> 5, lane = tid & 31;
    const int m0 = blockIdx.y * 128, n0 = blockIdx.x * 128;
    const int KT = K >> 6;
    const uint32_t bar = sbase + 2 * STAGE_BYTES;
    // bar+0,+8: full[0..1]   bar+16,+24: empty[0..1]

    if (tid == 0) {
        MBAR_INIT(bar + 0, 1);  MBAR_INIT(bar + 8, 1);
        MBAR_INIT(bar + 16, 8); MBAR_INIT(bar + 24, 8);
    }
    __syncthreads();

    if (wid == 8) {
        if (lane == 0) {
            const char* pAh = (const char*)Ahi + ((size_t)(m0 >> 7) * KT << 14);
            const char* pAl = (const char*)Alo + ((size_t)(m0 >> 7) * KT << 14);
            const char* pBh = (const char*)Bhi + ((size_t)(n0 >> 7) * KT << 14);
            const char* pBl = (const char*)Blo + ((size_t)(n0 >> 7) * KT << 14);
            int eph[2] = {1, 1};
            for (int i = 0; i < KT; i++) {
                int s = i & 1;
                MBAR_WAIT(bar + 16 + 8 * s, eph[s]);
                eph[s] ^= 1;
                MBAR_EXPECT_TX(bar + 8 * s, (uint32_t)STAGE_BYTES);
                uint32_t st = sbase + s * STAGE_BYTES;
                size_t ko = (size_t)i << 14;
                BULK_G2S(st,                 pAh + ko, TILE_BYTES, bar + 8 * s);
                BULK_G2S(st + TILE_BYTES,    pAl + ko, TILE_BYTES, bar + 8 * s);
                BULK_G2S(st + 2 * TILE_BYTES, pBh + ko, TILE_BYTES, bar + 8 * s);
                BULK_G2S(st + 3 * TILE_BYTES, pBl + ko, TILE_BYTES, bar + 8 * s);
            }
        }
        return;
    }

    // ---- compute warps 0..7: warp tile 64(m) x 32(n) ----
    const int wm = wid >> 2, wn = wid & 3;

    // per-lane unswizzled offsets + swizzle masks for ldmatrix
    // A frag i (i=0..3): rows wm*64 + i*16 + (lane&15), kbyte (lane>>4)*16
    uint32_t a_off[4], a_msk[4];
#pragma unroll
    for (int i = 0; i < 4; i++) {
        uint32_t row = wm * 64 + i * 16 + (lane & 15);
        uint32_t off = (row << 7) | ((lane >> 4) << 4);
        a_off[i] = off;
        a_msk[i] = (off >> 3) & 0x70;
    }
    // B pair p (p=0..1, covers n-frags 2p,2p+1): rows wn*32 + p*16 + ((lane>>4)<<3) + (lane&7),
    // kbyte ((lane>>3)&1)*16
    uint32_t b_off[2], b_msk[2];
#pragma unroll
    for (int p = 0; p < 2; p++) {
        uint32_t row = wn * 32 + p * 16 + ((lane >> 4) << 3) + (lane & 7);
        uint32_t off = (row << 7) | (((lane >> 3) & 1) << 4);
        b_off[p] = off;
        b_msk[p] = (off >> 3) & 0x70;
    }

    float acc[4][4][4];
#pragma unroll
    for (int i = 0; i < 4; i++)
#pragma unroll
        for (int j = 0; j < 4; j++)
#pragma unroll
            for (int e = 0; e < 4; e++) acc[i][j][e] = 0.f;

    int fph[2] = {0, 0};
    for (int it = 0; it < KT; it++) {
        int s = it & 1;
        MBAR_WAIT(bar + 8 * s, fph[s]);
        fph[s] ^= 1;
        uint32_t sAh = sbase + s * STAGE_BYTES;
        uint32_t sAl = sAh + TILE_BYTES;
        uint32_t sBh = sAh + 2 * TILE_BYTES;
        uint32_t sBl = sAh + 3 * TILE_BYTES;

#pragma unroll
        for (int ks = 0; ks < 4; ks++) {
            uint32_t kb = ks * 32;
            uint32_t ahi[4][4], alo[4][4], bhi[4][2], blo[4][2];
#pragma unroll
            for (int i = 0; i < 4; i++) {
                uint32_t sw = (a_off[i] + kb) ^ a_msk[i];
                ldsm_x4(ahi[i], sAh + sw);
                ldsm_x4(alo[i], sAl + sw);
            }
#pragma unroll
            for (int p = 0; p < 2; p++) {
                uint32_t sw = (b_off[p] + kb) ^ b_msk[p];
                uint32_t r[4];
                ldsm_x4(r, sBh + sw);
                bhi[2 * p][0] = r[0]; bhi[2 * p][1] = r[1];
                bhi[2 * p + 1][0] = r[2]; bhi[2 * p + 1][1] = r[3];
                ldsm_x4(r, sBl + sw);
                blo[2 * p][0] = r[0]; blo[2 * p][1] = r[1];
                blo[2 * p + 1][0] = r[2]; blo[2 * p + 1][1] = r[3];
            }
#pragma unroll
            for (int i = 0; i < 4; i++)
#pragma unroll
                for (int j = 0; j < 4; j++)
                    mma_bf16(acc[i][j], ahi[i], bhi[j]);
#pragma unroll
            for (int i = 0; i < 4; i++)
#pragma unroll
                for (int j = 0; j < 4; j++)
                    mma_bf16(acc[i][j], ahi[i], blo[j]);
#pragma unroll
            for (int i = 0; i < 4; i++)
#pragma unroll
                for (int j = 0; j < 4; j++)
                    mma_bf16(acc[i][j], alo[i], bhi[j]);
        }
        __syncwarp();
        if (lane == 0) MBAR_ARRIVE(bar + 16 + 8 * s);
    }

    // ---- epilogue: fragment -> C (row-major fp32) ----
    const int g_row = lane >> 2;
    const int g_col = (lane & 3) * 2;
#pragma unroll
    for (int i = 0; i < 4; i++) {
        size_t r0 = (size_t)m0 + wm * 64 + i * 16 + g_row;
#pragma unroll
        for (int j = 0; j < 4; j++) {
            int c = n0 + wn * 32 + j * 8 + g_col;
            float2 v0 = make_float2(acc[i][j][0], acc[i][j][1]);
            float2 v1 = make_float2(acc[i][j][2], acc[i][j][3]);
            *reinterpret_cast<float2*>(&C[r0 * N + c])       = v0;
            *reinterpret_cast<float2*>(&C[(r0 + 8) * N + c]) = v1;
        }
    }
}

// ---------------- launch ----------------
extern "C" void kernel_launch(void* const* d_in, const int* in_sizes, int n_in,
                              void* d_out, int out_size) {
    const float* x      = (const float*)d_in[0];
    const float* w_in   = (const float*)d_in[1];
    const float* w_out  = (const float*)d_in[2];
    const float* conv_w = (const float*)d_in[3];
    const float* conv_b = (const float*)d_in[4];
    const float* Dvec   = (const float*)d_in[5];
    float* out = (float*)d_out;

    float* xp; __nv_bfloat16 *xhi, *xlo, *wihi, *wilo, *hhi, *hlo, *wohi, *wolo;
    cudaGetSymbolAddress((void**)&xp,   g_xproj);
    cudaGetSymbolAddress((void**)&xhi,  g_x_hi);
    cudaGetSymbolAddress((void**)&xlo,  g_x_lo);
    cudaGetSymbolAddress((void**)&wihi, g_wi_hi);
    cudaGetSymbolAddress((void**)&wilo, g_wi_lo);
    cudaGetSymbolAddress((void**)&hhi,  g_h_hi);
    cudaGetSymbolAddress((void**)&hlo,  g_h_lo);
    cudaGetSymbolAddress((void**)&wohi, g_wo_hi);
    cudaGetSymbolAddress((void**)&wolo, g_wo_lo);

    cudaFuncSetAttribute(gemm_bf16x3, cudaFuncAttributeMaxDynamicSharedMemorySize, SMEM_REQ);

    // splits (tiled+swizzled bf16 hi/lo)
    {
        int t8 = MTOT * K1 / 8;
        split_tiled<<<(t8 + 255) / 256, 256>>>(x, xhi, xlo, t8, K1, 11);
    }
    {
        int t8 = N1 * K1 / 8;
        split_tiled<<<(t8 + 255) / 256, 256>>>(w_in, wihi, wilo, t8, K1, 11);
    }
    {
        int t8 = N2 * K2 / 8;
        split_tiled<<<(t8 + 255) / 256, 256>>>(w_out, wohi, wolo, t8, K2, 12);
    }

    // GEMM1: xproj[8192,8192] = x @ w_in^T
    gemm_bf16x3<<<dim3(N1 / 128, MTOT / 128), 288, SMEM_REQ>>>(xhi, xlo, wihi, wilo, xp, MTOT, N1, K1);

    // conv + gate -> h (split bf16)
    {
        int t8 = MTOT * DINNER / 8;
        conv_gate_split<<<(t8 + 255) / 256, 256>>>(xp, conv_w, conv_b, Dvec, hhi, hlo);
    }

    // GEMM2: out[8192,2048] = h @ w_out^T
    gemm_bf16x3<<<dim3(N2 / 128, MTOT / 128), 288, SMEM_REQ>>>(hhi, hlo, wohi, wolo, out, MTOT, N2, K2);
}

// round 4
// speedup vs baseline: 5.2111x; 1.4021x over previous
#include <cuda_runtime.h>
#include <cuda_fp16.h>
#include <stdint.h>

// Problem dims (fixed)
#define MTOT   8192     // B*T
#define SEQ    2048
#define N1     8192     // 2*d_inner
#define K1     2048     // d_model
#define DINNER 4096
#define N2     2048     // d_model
#define K2     4096     // d_inner

// ---------------- scratch (device globals; no runtime alloc) ----------------
__device__ float g_xproj[(size_t)MTOT * N1];     // 256 MB
__device__ __half g_x_hi [(size_t)MTOT * K1];
__device__ __half g_x_lo [(size_t)MTOT * K1];
__device__ __half g_wi_hi[(size_t)N1 * K1];
__device__ __half g_h_hi [(size_t)MTOT * K2];
__device__ __half g_h_lo [(size_t)MTOT * K2];
__device__ __half g_wo_hi[(size_t)N2 * K2];

// ---------------- PTX helpers (legal on plain sm_103) ----------------
__device__ __forceinline__ uint32_t smem_u32(const void* p) {
    uint32_t a;
    asm("{ .reg .u64 t; cvta.to.shared.u64 t, %1; cvt.u32.u64 %0, t; }" : "=r"(a) : "l"(p));
    return a;
}
#define MBAR_INIT(a, c) \
    asm volatile("mbarrier.init.shared.b64 [%0], %1;" :: "r"(a), "r"(c) : "memory")
#define MBAR_EXPECT_TX(a, b) \
    asm volatile("mbarrier.arrive.expect_tx.shared.b64 _, [%0], %1;" :: "r"(a), "r"(b) : "memory")
#define MBAR_ARRIVE(a) \
    asm volatile("mbarrier.arrive.shared.b64 _, [%0];" :: "r"(a) : "memory")
#define MBAR_WAIT(a, ph) do {                                                      \
    uint32_t _m = (a), _p = (ph), _d;                                              \
    asm volatile("{ .reg .pred p; mbarrier.try_wait.parity.acquire.cta.shared::cta.b64 p, [%1], %2;" \
                 " selp.b32 %0, 1, 0, p; }" : "=r"(_d) : "r"(_m), "r"(_p) : "memory"); \
    if (!_d) {                                                                     \
        asm volatile("{ .reg .pred P;\n"                                           \
                     "W%=: mbarrier.try_wait.parity.acquire.cta.shared::cta.b64 P, [%0], %1, 0x989680;\n" \
                     "@P bra.uni D%=;\n bra.uni W%=;\nD%=: }"                      \
                     :: "r"(_m), "r"(_p) : "memory");                              \
    } } while (0)
#define BULK_G2S(sa, gp, bytes, mb) \
    asm volatile("cp.async.bulk.shared::cluster.global.mbarrier::complete_tx::bytes [%0], [%1], %2, [%3];" \
                 :: "r"(sa), "l"(gp), "r"(bytes), "r"(mb) : "memory")

__device__ __forceinline__ void ldsm_x4(uint32_t* r, uint32_t addr) {
    asm volatile("ldmatrix.sync.aligned.m8n8.x4.shared.b16 {%0,%1,%2,%3}, [%4];"
                 : "=r"(r[0]), "=r"(r[1]), "=r"(r[2]), "=r"(r[3]) : "r"(addr));
}
__device__ __forceinline__ void mma_f16(float* d, const uint32_t* a, const uint32_t* b) {
    asm volatile("mma.sync.aligned.m16n8k16.row.col.f32.f16.f16.f32 "
                 "{%0,%1,%2,%3},{%4,%5,%6,%7},{%8,%9},{%0,%1,%2,%3};"
                 : "+f"(d[0]), "+f"(d[1]), "+f"(d[2]), "+f"(d[3])
                 : "r"(a[0]), "r"(a[1]), "r"(a[2]), "r"(a[3]), "r"(b[0]), "r"(b[1]));
}

// Tiled+swizzled f16 layout: tiles of 128 rows x 64 cols (16 KB), k-tile fastest.
// Within a tile: SW128 swizzle of (row*128 + col*2).
__device__ __forceinline__ size_t tiled_off(int r, int c, int K) {
    size_t tile = ((size_t)(r >> 7) * (size_t)(K >> 6) + (size_t)(c >> 6)) << 14;
    uint32_t off = ((uint32_t)(r & 127) << 7) | ((uint32_t)(c & 63) << 1);
    off ^= (off >> 3) & 0x70;
    return tile + off;
}

// ---------------- split fp32 -> (hi,lo) fp16 in tiled layout ----------------
__global__ void split_pair_f16(const float* __restrict__ src, __half* __restrict__ hi,
                               __half* __restrict__ lo, int total8, int K, int kshift) {
    int idx = blockIdx.x * blockDim.x + threadIdx.x;
    if (idx >= total8) return;
    int e0 = idx << 3;
    int r = e0 >> kshift;
    int c = e0 & (K - 1);
    const float* p = src + (size_t)r * K + c;
    float4 v0 = *reinterpret_cast<const float4*>(p);
    float4 v1 = *reinterpret_cast<const float4*>(p + 4);
    float xs[8] = {v0.x, v0.y, v0.z, v0.w, v1.x, v1.y, v1.z, v1.w};
    __align__(16) __half hv[8];
    __align__(16) __half lv[8];
#pragma unroll
    for (int j = 0; j < 8; j++) {
        __half h = __float2half_rn(xs[j]);
        hv[j] = h;
        lv[j] = __float2half_rn(xs[j] - __half2float(h));
    }
    size_t o = tiled_off(r, c, K);
    *reinterpret_cast<uint4*>((char*)hi + o) = *reinterpret_cast<const uint4*>(hv);
    *reinterpret_cast<uint4*>((char*)lo + o) = *reinterpret_cast<const uint4*>(lv);
}

// ---------------- round fp32 -> hi fp16 only (for B / weights) ----------------
__global__ void split_hi_f16(const float* __restrict__ src, __half* __restrict__ hi,
                             int total8, int K, int kshift) {
    int idx = blockIdx.x * blockDim.x + threadIdx.x;
    if (idx >= total8) return;
    int e0 = idx << 3;
    int r = e0 >> kshift;
    int c = e0 & (K - 1);
    const float* p = src + (size_t)r * K + c;
    float4 v0 = *reinterpret_cast<const float4*>(p);
    float4 v1 = *reinterpret_cast<const float4*>(p + 4);
    float xs[8] = {v0.x, v0.y, v0.z, v0.w, v1.x, v1.y, v1.z, v1.w};
    __align__(16) __half hv[8];
#pragma unroll
    for (int j = 0; j < 8; j++) hv[j] = __float2half_rn(xs[j]);
    size_t o = tiled_off(r, c, K);
    *reinterpret_cast<uint4*>((char*)hi + o) = *reinterpret_cast<const uint4*>(hv);
}

// ------- depthwise causal conv(4) + SiLU gate, output split to fp16 hi/lo -------
__global__ void conv_gate_split(const float* __restrict__ xp, const float* __restrict__ cw,
                                const float* __restrict__ cb, const float* __restrict__ Dv,
                                __half* __restrict__ hhi, __half* __restrict__ hlo) {
    int idx = blockIdx.x * blockDim.x + threadIdx.x;
    if (idx >= (MTOT * DINNER) / 8) return;
    int d0 = (idx & 511) << 3;
    int m  = idx >> 9;
    int t  = m & (SEQ - 1);
    const float* row = xp + (size_t)m * N1 + d0;

    float acc[8];
    {
        float4 b0 = *reinterpret_cast<const float4*>(cb + d0);
        float4 b1 = *reinterpret_cast<const float4*>(cb + d0 + 4);
        acc[0]=b0.x; acc[1]=b0.y; acc[2]=b0.z; acc[3]=b0.w;
        acc[4]=b1.x; acc[5]=b1.y; acc[6]=b1.z; acc[7]=b1.w;
    }
    float4 cwv[8];
#pragma unroll
    for (int e = 0; e < 8; e++) cwv[e] = *reinterpret_cast<const float4*>(cw + (size_t)(d0 + e) * 4);

#pragma unroll
    for (int j = 0; j < 4; j++) {
        if (t >= j) {
            const float* rp = row - (size_t)j * N1;
            float4 a = *reinterpret_cast<const float4*>(rp);
            float4 b = *reinterpret_cast<const float4*>(rp + 4);
            float xv[8] = {a.x, a.y, a.z, a.w, b.x, b.y, b.z, b.w};
#pragma unroll
            for (int e = 0; e < 8; e++) {
                float w = (j == 0) ? cwv[e].w : (j == 1) ? cwv[e].z : (j == 2) ? cwv[e].y : cwv[e].x;
                acc[e] = fmaf(xv[e], w, acc[e]);
            }
        }
    }
    float4 g0 = *reinterpret_cast<const float4*>(row + DINNER);
    float4 g1 = *reinterpret_cast<const float4*>(row + DINNER + 4);
    float gv[8] = {g0.x, g0.y, g0.z, g0.w, g1.x, g1.y, g1.z, g1.w};
    float4 dv0 = *reinterpret_cast<const float4*>(Dv + d0);
    float4 dv1 = *reinterpret_cast<const float4*>(Dv + d0 + 4);
    float dv[8] = {dv0.x, dv0.y, dv0.z, dv0.w, dv1.x, dv1.y, dv1.z, dv1.w};

    __align__(16) __half hv[8];
    __align__(16) __half lv[8];
#pragma unroll
    for (int e = 0; e < 8; e++) {
        float s1 = acc[e] / (1.f + __expf(-acc[e]));
        float s2 = gv[e] / (1.f + __expf(-gv[e]));
        float val = s1 * dv[e] * s2;
        __half h = __float2half_rn(val);
        hv[e] = h;
        lv[e] = __float2half_rn(val - __half2float(h));
    }
    size_t o = tiled_off(m, d0, K2);
    *reinterpret_cast<uint4*>((char*)hhi + o) = *reinterpret_cast<const uint4*>(hv);
    *reinterpret_cast<uint4*>((char*)hlo + o) = *reinterpret_cast<const uint4*>(lv);
}

// ---------------- fp16x2 HMMA GEMM: C[M,N] = (Ahi+Alo)[M,K] * Bhi[N,K]^T ----------------
// CTA tile 128x128, BK=64, 3-stage async pipeline (48 KB/stage), 8 compute warps + 1 producer.
#define TILE_BYTES  16384
#define STAGE_BYTES 49152      // A_hi A_lo B_hi
#define NSTAGE      3
#define SMEM_REQ    (NSTAGE * STAGE_BYTES + 1024 + 128)

__global__ void __launch_bounds__(288, 1)
gemm_f16x2(const __half* __restrict__ Ahi, const __half* __restrict__ Alo,
           const __half* __restrict__ Bhi,
           float* __restrict__ C, int M, int N, int K) {
    extern __shared__ char smem_raw[];
    uint32_t sbase = (smem_u32(smem_raw) + 1023) & ~1023u;
    const int tid = threadIdx.x, wid = tid >> 5, lane = tid & 31;
    const int m0 = blockIdx.y * 128, n0 = blockIdx.x * 128;
    const int KT = K >> 6;
    const uint32_t bar = sbase + NSTAGE * STAGE_BYTES;
    // bar + 8*s: full[s]   bar + 64 + 8*s: empty[s]

    if (tid == 0) {
#pragma unroll
        for (int s = 0; s < NSTAGE; s++) {
            MBAR_INIT(bar + 8 * s, 1);
            MBAR_INIT(bar + 64 + 8 * s, 8);
        }
    }
    __syncthreads();

    if (wid == 8) {
        if (lane == 0) {
            const char* pAh = (const char*)Ahi + ((size_t)(m0 >> 7) * KT << 14);
            const char* pAl = (const char*)Alo + ((size_t)(m0 >> 7) * KT << 14);
            const char* pBh = (const char*)Bhi + ((size_t)(n0 >> 7) * KT << 14);
            int eph[NSTAGE] = {1, 1, 1};
            int s = 0;
            for (int i = 0; i < KT; i++) {
                MBAR_WAIT(bar + 64 + 8 * s, eph[s]);
                eph[s] ^= 1;
                MBAR_EXPECT_TX(bar + 8 * s, (uint32_t)STAGE_BYTES);
                uint32_t st = sbase + s * STAGE_BYTES;
                size_t ko = (size_t)i << 14;
                BULK_G2S(st,                  pAh + ko, TILE_BYTES, bar + 8 * s);
                BULK_G2S(st + TILE_BYTES,     pAl + ko, TILE_BYTES, bar + 8 * s);
                BULK_G2S(st + 2 * TILE_BYTES, pBh + ko, TILE_BYTES, bar + 8 * s);
                if (++s == NSTAGE) s = 0;
            }
        }
        return;
    }

    // ---- compute warps 0..7: warp tile 64(m) x 32(n) ----
    const int wm = wid >> 2, wn = wid & 3;

    uint32_t a_off[4], a_msk[4];
#pragma unroll
    for (int i = 0; i < 4; i++) {
        uint32_t row = wm * 64 + i * 16 + (lane & 15);
        uint32_t off = (row << 7) | ((lane >> 4) << 4);
        a_off[i] = off;
        a_msk[i] = (off >> 3) & 0x70;
    }
    uint32_t b_off[2], b_msk[2];
#pragma unroll
    for (int p = 0; p < 2; p++) {
        uint32_t row = wn * 32 + p * 16 + ((lane >> 4) << 3) + (lane & 7);
        uint32_t off = (row << 7) | (((lane >> 3) & 1) << 4);
        b_off[p] = off;
        b_msk[p] = (off >> 3) & 0x70;
    }

    float acc[4][4][4];
#pragma unroll
    for (int i = 0; i < 4; i++)
#pragma unroll
        for (int j = 0; j < 4; j++)
#pragma unroll
            for (int e = 0; e < 4; e++) acc[i][j][e] = 0.f;

    int fph[NSTAGE] = {0, 0, 0};
    int s = 0;
    for (int it = 0; it < KT; it++) {
        MBAR_WAIT(bar + 8 * s, fph[s]);
        fph[s] ^= 1;
        uint32_t sAh = sbase + s * STAGE_BYTES;
        uint32_t sAl = sAh + TILE_BYTES;
        uint32_t sBh = sAh + 2 * TILE_BYTES;

#pragma unroll
        for (int ks = 0; ks < 4; ks++) {
            uint32_t kb = ks * 32;
            uint32_t ahi[4][4], alo[4][4], bhi[4][2];
#pragma unroll
            for (int i = 0; i < 4; i++) {
                uint32_t sw = (a_off[i] + kb) ^ a_msk[i];
                ldsm_x4(ahi[i], sAh + sw);
                ldsm_x4(alo[i], sAl + sw);
            }
#pragma unroll
            for (int p = 0; p < 2; p++) {
                uint32_t sw = (b_off[p] + kb) ^ b_msk[p];
                uint32_t r[4];
                ldsm_x4(r, sBh + sw);
                bhi[2 * p][0] = r[0]; bhi[2 * p][1] = r[1];
                bhi[2 * p + 1][0] = r[2]; bhi[2 * p + 1][1] = r[3];
            }
#pragma unroll
            for (int i = 0; i < 4; i++)
#pragma unroll
                for (int j = 0; j < 4; j++)
                    mma_f16(acc[i][j], ahi[i], bhi[j]);
#pragma unroll
            for (int i = 0; i < 4; i++)
#pragma unroll
                for (int j = 0; j < 4; j++)
                    mma_f16(acc[i][j], alo[i], bhi[j]);
        }
        __syncwarp();
        if (lane == 0) MBAR_ARRIVE(bar + 64 + 8 * s);
        if (++s == NSTAGE) s = 0;
    }

    // ---- epilogue: fragment -> C (row-major fp32) ----
    const int g_row = lane >> 2;
    const int g_col = (lane & 3) * 2;
#pragma unroll
    for (int i = 0; i < 4; i++) {
        size_t r0 = (size_t)m0 + wm * 64 + i * 16 + g_row;
#pragma unroll
        for (int j = 0; j < 4; j++) {
            int c = n0 + wn * 32 + j * 8 + g_col;
            float2 v0 = make_float2(acc[i][j][0], acc[i][j][1]);
            float2 v1 = make_float2(acc[i][j][2], acc[i][j][3]);
            *reinterpret_cast<float2*>(&C[r0 * N + c])       = v0;
            *reinterpret_cast<float2*>(&C[(r0 + 8) * N + c]) = v1;
        }
    }
}

// ---------------- launch ----------------
extern "C" void kernel_launch(void* const* d_in, const int* in_sizes, int n_in,
                              void* d_out, int out_size) {
    const float* x      = (const float*)d_in[0];
    const float* w_in   = (const float*)d_in[1];
    const float* w_out  = (const float*)d_in[2];
    const float* conv_w = (const float*)d_in[3];
    const float* conv_b = (const float*)d_in[4];
    const float* Dvec   = (const float*)d_in[5];
    float* out = (float*)d_out;

    float* xp; __half *xhi, *xlo, *wihi, *hhi, *hlo, *wohi;
    cudaGetSymbolAddress((void**)&xp,   g_xproj);
    cudaGetSymbolAddress((void**)&xhi,  g_x_hi);
    cudaGetSymbolAddress((void**)&xlo,  g_x_lo);
    cudaGetSymbolAddress((void**)&wihi, g_wi_hi);
    cudaGetSymbolAddress((void**)&hhi,  g_h_hi);
    cudaGetSymbolAddress((void**)&hlo,  g_h_lo);
    cudaGetSymbolAddress((void**)&wohi, g_wo_hi);

    cudaFuncSetAttribute(gemm_f16x2, cudaFuncAttributeMaxDynamicSharedMemorySize, SMEM_REQ);

    // splits (tiled+swizzled fp16)
    {
        int t8 = MTOT * K1 / 8;
        split_pair_f16<<<(t8 + 255) / 256, 256>>>(x, xhi, xlo, t8, K1, 11);
    }
    {
        int t8 = N1 * K1 / 8;
        split_hi_f16<<<(t8 + 255) / 256, 256>>>(w_in, wihi, t8, K1, 11);
    }
    {
        int t8 = N2 * K2 / 8;
        split_hi_f16<<<(t8 + 255) / 256, 256>>>(w_out, wohi, t8, K2, 12);
    }

    // GEMM1: xproj[8192,8192] = x @ w_in^T
    gemm_f16x2<<<dim3(N1 / 128, MTOT / 128), 288, SMEM_REQ>>>(xhi, xlo, wihi, xp, MTOT, N1, K1);

    // conv + gate -> h (split fp16)
    {
        int t8 = MTOT * DINNER / 8;
        conv_gate_split<<<(t8 + 255) / 256, 256>>>(xp, conv_w, conv_b, Dvec, hhi, hlo);
    }

    // GEMM2: out[8192,2048] = h @ w_out^T
    gemm_f16x2<<<dim3(N2 / 128, MTOT / 128), 288, SMEM_REQ>>>(hhi, hlo, wohi, out, MTOT, N2, K2);
}